// round 1
// baseline (speedup 1.0000x reference)
#include <cuda_runtime.h>
#include <math.h>

#define NN   96
#define HH   192
#define EPSV 1e-6f
#define TPB  256
#define YPAD 100   // stride in floats: tid*100*4 bytes is 16B aligned; (4*lane+k)%32 conflict-free for LDS.128

__device__ float g_D[NN * NN];     // DCT-II matrix, row-major [k][i]
__device__ float g_W2t[HH * NN];   // W2 transposed: W2t[j][k] = W2[k][j]

// Precompute DCT matrix and transposed W2 (cheap, launched every call: deterministic).
__global__ void prep_kernel(const float* __restrict__ W2) {
    int t = blockIdx.x * blockDim.x + threadIdx.x;
    if (t < NN * NN) {
        int k = t / NN, i = t % NN;
        double v = 2.0 * cos(3.14159265358979323846 * (2.0 * i + 1.0) * (double)k / (2.0 * NN));
        g_D[t] = (float)v;
    }
    if (t < HH * NN) {
        int j = t / NN, k = t % NN;
        g_W2t[t] = W2[k * HH + j];
    }
}

#define FMA4(acc_x, acc_y, acc_z, acc_w, a, w)      \
    do {                                            \
        acc_x = fmaf((a).x, (w).x, acc_x);          \
        acc_y = fmaf((a).y, (w).y, acc_y);          \
        acc_z = fmaf((a).z, (w).z, acc_z);          \
        acc_w = fmaf((a).w, (w).w, acc_w);          \
    } while (0)

extern __shared__ float s_y[];  // TPB * YPAD floats

__global__ __launch_bounds__(TPB, 1)
void fused_kernel(const float* __restrict__ x,
                  const float* __restrict__ W1,
                  const float* __restrict__ gamma,
                  const float* __restrict__ beta,
                  float* __restrict__ out,
                  int rows) {
    int row = blockIdx.x * TPB + threadIdx.x;
    if (row >= rows) return;  // no __syncthreads in this kernel, early exit is safe

    float* Ys = s_y + threadIdx.x * YPAD;
    float4* Ys4 = (float4*)Ys;

    const float4* xrow = (const float4*)(x + (size_t)row * NN);

    // ---- Load x row into registers ----
    float4 xv[NN / 4];
#pragma unroll
    for (int i = 0; i < NN / 4; i++) xv[i] = xrow[i];

    // ---- Phase 1: DCT  y[k] = sum_i x[i] * D[k][i] ----
    for (int k = 0; k < NN; k++) {
        const float4* dr = (const float4*)(g_D + k * NN);
        float ax = 0.f, ay = 0.f, az = 0.f, aw = 0.f;
#pragma unroll
        for (int i = 0; i < NN / 4; i++) {
            float4 w = dr[i];
            FMA4(ax, ay, az, aw, xv[i], w);
        }
        Ys[k] = (ax + ay) + (az + aw);
    }

    // ---- LayerNorm 1 (over 96) ----
    float mu = 0.f;
#pragma unroll
    for (int i = 0; i < NN / 4; i++) {
        float4 y = Ys4[i];
        mu += (y.x + y.y) + (y.z + y.w);
    }
    mu *= (1.0f / NN);
    float var = 0.f;
#pragma unroll
    for (int i = 0; i < NN / 4; i++) {
        float4 y = Ys4[i];
        float dx = y.x - mu, dy = y.y - mu, dz = y.z - mu, dw = y.w - mu;
        var = fmaf(dx, dx, var);
        var = fmaf(dy, dy, var);
        var = fmaf(dz, dz, var);
        var = fmaf(dw, dw, var);
    }
    float rs = rsqrtf(var * (1.0f / NN) + EPSV);

    const float4* g4 = (const float4*)gamma;
    const float4* b4 = (const float4*)beta;

    float4 lr[NN / 4];
#pragma unroll
    for (int i = 0; i < NN / 4; i++) {
        float4 y = Ys4[i];
        float4 g = g4[i];
        float4 b = b4[i];
        lr[i].x = fmaf((y.x - mu) * rs, g.x, b.x);
        lr[i].y = fmaf((y.y - mu) * rs, g.y, b.y);
        lr[i].z = fmaf((y.z - mu) * rs, g.z, b.z);
        lr[i].w = fmaf((y.w - mu) * rs, g.w, b.w);
    }

    // ---- Phase 2+3: h = relu(lr @ W1^T), s_acc += h[j] * W2t[j][:]  (streamed over j) ----
    float4 sa[NN / 4];
#pragma unroll
    for (int i = 0; i < NN / 4; i++) sa[i] = make_float4(0.f, 0.f, 0.f, 0.f);

    for (int j = 0; j < HH; j++) {
        const float4* w1r = (const float4*)(W1 + j * NN);
        float hx = 0.f, hy = 0.f, hz = 0.f, hw = 0.f;
#pragma unroll
        for (int i = 0; i < NN / 4; i++) {
            float4 w = w1r[i];
            FMA4(hx, hy, hz, hw, lr[i], w);
        }
        float h = (hx + hy) + (hz + hw);
        h = fmaxf(h, 0.f);

        const float4* w2r = (const float4*)(g_W2t + j * NN);
#pragma unroll
        for (int i = 0; i < NN / 4; i++) {
            float4 w = w2r[i];
            sa[i].x = fmaf(h, w.x, sa[i].x);
            sa[i].y = fmaf(h, w.y, sa[i].y);
            sa[i].z = fmaf(h, w.z, sa[i].z);
            sa[i].w = fmaf(h, w.w, sa[i].w);
        }
    }

    // ---- sigmoid ----
#pragma unroll
    for (int i = 0; i < NN / 4; i++) {
        sa[i].x = 1.f / (1.f + expf(-sa[i].x));
        sa[i].y = 1.f / (1.f + expf(-sa[i].y));
        sa[i].z = 1.f / (1.f + expf(-sa[i].z));
        sa[i].w = 1.f / (1.f + expf(-sa[i].w));
    }

    // ---- LayerNorm 2 ----
    float mu2 = 0.f;
#pragma unroll
    for (int i = 0; i < NN / 4; i++)
        mu2 += (sa[i].x + sa[i].y) + (sa[i].z + sa[i].w);
    mu2 *= (1.0f / NN);
    float v2 = 0.f;
#pragma unroll
    for (int i = 0; i < NN / 4; i++) {
        float dx = sa[i].x - mu2, dy = sa[i].y - mu2, dz = sa[i].z - mu2, dw = sa[i].w - mu2;
        v2 = fmaf(dx, dx, v2);
        v2 = fmaf(dy, dy, v2);
        v2 = fmaf(dz, dz, v2);
        v2 = fmaf(dw, dw, v2);
    }
    float rs2 = rsqrtf(v2 * (1.0f / NN) + EPSV);

    // ---- out = x * (LN2(s) * gamma + beta) ----
    float4* orow = (float4*)(out + (size_t)row * NN);
#pragma unroll
    for (int i = 0; i < NN / 4; i++) {
        float4 g = g4[i];
        float4 b = b4[i];
        float4 xr = xrow[i];
        float4 o;
        o.x = xr.x * fmaf((sa[i].x - mu2) * rs2, g.x, b.x);
        o.y = xr.y * fmaf((sa[i].y - mu2) * rs2, g.y, b.y);
        o.z = xr.z * fmaf((sa[i].z - mu2) * rs2, g.z, b.z);
        o.w = xr.w * fmaf((sa[i].w - mu2) * rs2, g.w, b.w);
        orow[i] = o;
    }
}

extern "C" void kernel_launch(void* const* d_in, const int* in_sizes, int n_in,
                              void* d_out, int out_size) {
    const float* x     = (const float*)d_in[0];
    const float* W1    = (const float*)d_in[1];
    const float* W2    = (const float*)d_in[2];
    const float* gamma = (const float*)d_in[3];
    const float* beta  = (const float*)d_in[4];
    float* out = (float*)d_out;

    int rows = in_sizes[0] / NN;

    prep_kernel<<<(HH * NN + 255) / 256, 256>>>(W2);

    size_t shmem = (size_t)TPB * YPAD * sizeof(float);
    cudaFuncSetAttribute(fused_kernel, cudaFuncAttributeMaxDynamicSharedMemorySize, (int)shmem);

    int grid = (rows + TPB - 1) / TPB;
    fused_kernel<<<grid, TPB, shmem>>>(x, W1, gamma, beta, out, rows);
}

// round 3
// speedup vs baseline: 15.8178x; 15.8178x over previous
#include <cuda_runtime.h>
#include <cuda_fp16.h>
#include <math.h>
#include <stdint.h>

#define NN   96
#define HH   192
#define TPB  256
#define EPSV 1e-6f

// ---------------- smem layout (bytes) ----------------
#define OFF_G     0                      // float gamma[96]
#define OFF_B     384                    // float beta[96]
#define OFF_DHI   1024
#define STR_D     208                    // 104 f16 per row (conflict-free ldmatrix)
#define SZ_D      (96 * 208)             // 19968
#define OFF_DLO   (OFF_DHI + SZ_D)
#define OFF_W1HI  (OFF_DLO + SZ_D)
#define STR_W1    208
#define SZ_W1     (192 * 208)            // 39936
#define OFF_W1LO  (OFF_W1HI + SZ_W1)
#define OFF_W2HI  (OFF_W1LO + SZ_W1)
#define STR_W2    400                    // 200 f16 per row
#define SZ_W2     (96 * 400)             // 38400
#define OFF_W2LO  (OFF_W2HI + SZ_W2)
#define SMEM_TOTAL (OFF_W2LO + SZ_W2)    // 197632 bytes

__device__ __forceinline__ uint32_t smem_u32(const void* p) {
    uint32_t a;
    asm("{ .reg .u64 t; cvta.to.shared.u64 t, %1; cvt.u32.u64 %0, t; }" : "=r"(a) : "l"(p));
    return a;
}

#define LDSM4(d0, d1, d2, d3, a) \
    asm volatile("ldmatrix.sync.aligned.m8n8.x4.shared.b16 {%0,%1,%2,%3}, [%4];" \
        : "=r"(d0), "=r"(d1), "=r"(d2), "=r"(d3) : "r"(a))

// D (m16n8) += A (m16k16, row) * B (k16n8, col).  A = 4 regs, B = 2 regs, acc = 4 f32.
#define MMA(ac, A, b0, b1) \
    asm volatile("mma.sync.aligned.m16n8k16.row.col.f32.f16.f16.f32 " \
        "{%0,%1,%2,%3}, {%4,%5,%6,%7}, {%8,%9}, {%0,%1,%2,%3};" \
        : "+f"((ac)[0]), "+f"((ac)[1]), "+f"((ac)[2]), "+f"((ac)[3]) \
        : "r"((A)[0]), "r"((A)[1]), "r"((A)[2]), "r"((A)[3]), "r"(b0), "r"(b1))

// split (a,b) into packed f16x2 hi and lo words (lo = residual)
__device__ __forceinline__ void sp2(float a, float b, uint32_t& hi, uint32_t& lo) {
    __half2 h = __floats2half2_rn(a, b);
    float ra = a - __low2float(h);
    float rb = b - __high2float(h);
    __half2 l = __floats2half2_rn(ra, rb);
    hi = *(uint32_t*)&h;
    lo = *(uint32_t*)&l;
}

// the 6-mma split group: (Ahi*Bhi + Ahi*Blo + Alo*Bhi) for 2 k-halves
#define MMA6(ac, A0h, A0l, A1h, A1l, B_h, B_l)       \
    do {                                             \
        MMA(ac, A0h, (B_h)[0], (B_h)[1]);            \
        MMA(ac, A0h, (B_l)[0], (B_l)[1]);            \
        MMA(ac, A0l, (B_h)[0], (B_h)[1]);            \
        MMA(ac, A1h, (B_h)[2], (B_h)[3]);            \
        MMA(ac, A1h, (B_l)[2], (B_l)[3]);            \
        MMA(ac, A1l, (B_h)[2], (B_h)[3]);            \
    } while (0)

extern __shared__ char sm[];

__global__ void __launch_bounds__(TPB, 1)
fused_mma_kernel(const float* __restrict__ x,
                 const float* __restrict__ W1,
                 const float* __restrict__ W2,
                 const float* __restrict__ gamma,
                 const float* __restrict__ beta,
                 float* __restrict__ out,
                 int rows) {
    const int tid  = threadIdx.x;
    const int lane = tid & 31;
    const int warp = tid >> 5;
    const int gid  = lane >> 2;   // row within m8 group
    const int tig  = lane & 3;    // col-pair index
    const uint32_t sb = smem_u32(sm);

    float* sg = (float*)(sm + OFF_G);
    float* sbt = (float*)(sm + OFF_B);

    // ---------------- one-time weight staging (per CTA) ----------------
    if (tid < 96) { sg[tid] = gamma[tid]; sbt[tid] = beta[tid]; }
    const float PI192 = 0.016362461737446838f;  // pi/192
    for (int t = tid; t < 96 * 96; t += TPB) {
        int n = t / 96, i = t % 96;
        int m = ((2 * i + 1) * n) % 384;
        float v = 2.0f * cosf(PI192 * (float)m);
        __half h = __float2half_rn(v);
        __half l = __float2half_rn(v - __half2float(h));
        *(__half*)(sm + OFF_DHI + n * STR_D + i * 2) = h;
        *(__half*)(sm + OFF_DLO + n * STR_D + i * 2) = l;
    }
    for (int t = tid; t < 192 * 96; t += TPB) {
        int n = t / 96, i = t % 96;
        float v = W1[t];
        __half h = __float2half_rn(v);
        __half l = __float2half_rn(v - __half2float(h));
        *(__half*)(sm + OFF_W1HI + n * STR_W1 + i * 2) = h;
        *(__half*)(sm + OFF_W1LO + n * STR_W1 + i * 2) = l;
    }
    for (int t = tid; t < 96 * 192; t += TPB) {
        int n = t / 192, i = t % 192;
        float v = W2[t];
        __half h = __float2half_rn(v);
        __half l = __float2half_rn(v - __half2float(h));
        *(__half*)(sm + OFF_W2HI + n * STR_W2 + i * 2) = h;
        *(__half*)(sm + OFF_W2LO + n * STR_W2 + i * 2) = l;
    }
    __syncthreads();

    // per-lane ldmatrix base addresses (lane%8 = row in block, lane/8 = k-half block)
    const uint32_t lrow = lane & 7;
    const uint32_t lkb  = (uint32_t)(lane >> 3) * 16;
    const uint32_t bDh  = sb + OFF_DHI  + lrow * STR_D  + lkb;
    const uint32_t bDl  = sb + OFF_DLO  + lrow * STR_D  + lkb;
    const uint32_t bW1h = sb + OFF_W1HI + lrow * STR_W1 + lkb;
    const uint32_t bW1l = sb + OFF_W1LO + lrow * STR_W1 + lkb;
    const uint32_t bW2h = sb + OFF_W2HI + lrow * STR_W2 + lkb;
    const uint32_t bW2l = sb + OFF_W2LO + lrow * STR_W2 + lkb;

    const int ntiles = (rows + 127) >> 7;

    for (int tile = blockIdx.x; tile < ntiles; tile += gridDim.x) {
        const int r0 = tile * 128 + warp * 16 + gid;
        const int r1 = r0 + 8;
        const int r0c = min(r0, rows - 1);
        const int r1c = min(r1, rows - 1);
        const float* xr0 = x + (size_t)r0c * NN;
        const float* xr1 = x + (size_t)r1c * NN;

        // ================= GEMM1: Y = X @ D^T  (12 n-tiles, 6 k-tiles) =================
        float acc[12][4];
#pragma unroll
        for (int i = 0; i < 12; i++) { acc[i][0] = acc[i][1] = acc[i][2] = acc[i][3] = 0.f; }

#pragma unroll
        for (int ktp = 0; ktp < 3; ktp++) {
            uint32_t ah0[4], al0[4], ah1[4], al1[4];
            {
                int kb = 32 * ktp + 2 * tig;
                float2 v0 = *(const float2*)(xr0 + kb);
                float2 v1 = *(const float2*)(xr1 + kb);
                float2 v2 = *(const float2*)(xr0 + kb + 8);
                float2 v3 = *(const float2*)(xr1 + kb + 8);
                sp2(v0.x, v0.y, ah0[0], al0[0]);
                sp2(v1.x, v1.y, ah0[1], al0[1]);
                sp2(v2.x, v2.y, ah0[2], al0[2]);
                sp2(v3.x, v3.y, ah0[3], al0[3]);
                float2 u0 = *(const float2*)(xr0 + kb + 16);
                float2 u1 = *(const float2*)(xr1 + kb + 16);
                float2 u2 = *(const float2*)(xr0 + kb + 24);
                float2 u3 = *(const float2*)(xr1 + kb + 24);
                sp2(u0.x, u0.y, ah1[0], al1[0]);
                sp2(u1.x, u1.y, ah1[1], al1[1]);
                sp2(u2.x, u2.y, ah1[2], al1[2]);
                sp2(u3.x, u3.y, ah1[3], al1[3]);
            }
#pragma unroll
            for (int g = 0; g < 3; g++) {
                uint32_t bh[4][4], bl[4][4];
#pragma unroll
                for (int j = 0; j < 4; j++) {
                    int nt = 4 * g + j;
                    LDSM4(bh[j][0], bh[j][1], bh[j][2], bh[j][3], bDh + nt * (8 * STR_D) + ktp * 64);
                    LDSM4(bl[j][0], bl[j][1], bl[j][2], bl[j][3], bDl + nt * (8 * STR_D) + ktp * 64);
                }
#pragma unroll
                for (int j = 0; j < 4; j++) MMA(acc[4 * g + j], ah0, bh[j][0], bh[j][1]);
#pragma unroll
                for (int j = 0; j < 4; j++) MMA(acc[4 * g + j], ah0, bl[j][0], bl[j][1]);
#pragma unroll
                for (int j = 0; j < 4; j++) MMA(acc[4 * g + j], al0, bh[j][0], bh[j][1]);
#pragma unroll
                for (int j = 0; j < 4; j++) MMA(acc[4 * g + j], ah1, bh[j][2], bh[j][3]);
#pragma unroll
                for (int j = 0; j < 4; j++) MMA(acc[4 * g + j], ah1, bl[j][2], bl[j][3]);
#pragma unroll
                for (int j = 0; j < 4; j++) MMA(acc[4 * g + j], al1, bh[j][2], bh[j][3]);
            }
        }

        // ================= LayerNorm 1 (rows r0, r1) =================
        float s0 = 0.f, s1 = 0.f;
#pragma unroll
        for (int nt = 0; nt < 12; nt++) { s0 += acc[nt][0] + acc[nt][1]; s1 += acc[nt][2] + acc[nt][3]; }
        s0 += __shfl_xor_sync(0xffffffffu, s0, 1); s0 += __shfl_xor_sync(0xffffffffu, s0, 2);
        s1 += __shfl_xor_sync(0xffffffffu, s1, 1); s1 += __shfl_xor_sync(0xffffffffu, s1, 2);
        float mu0 = s0 * (1.0f / 96.0f), mu1 = s1 * (1.0f / 96.0f);
        float q0 = 0.f, q1 = 0.f;
#pragma unroll
        for (int nt = 0; nt < 12; nt++) {
            float d;
            d = acc[nt][0] - mu0; q0 = fmaf(d, d, q0);
            d = acc[nt][1] - mu0; q0 = fmaf(d, d, q0);
            d = acc[nt][2] - mu1; q1 = fmaf(d, d, q1);
            d = acc[nt][3] - mu1; q1 = fmaf(d, d, q1);
        }
        q0 += __shfl_xor_sync(0xffffffffu, q0, 1); q0 += __shfl_xor_sync(0xffffffffu, q0, 2);
        q1 += __shfl_xor_sync(0xffffffffu, q1, 1); q1 += __shfl_xor_sync(0xffffffffu, q1, 2);
        float rs0 = rsqrtf(q0 * (1.0f / 96.0f) + EPSV);
        float rs1 = rsqrtf(q1 * (1.0f / 96.0f) + EPSV);

        // convert LN output into GEMM2 A-fragments (D-frag == A-frag alignment)
        uint32_t a2h[6][4], a2l[6][4];
#pragma unroll
        for (int nt = 0; nt < 12; nt++) {
            float2 gv = *(const float2*)(sg  + 8 * nt + 2 * tig);
            float2 bv = *(const float2*)(sbt + 8 * nt + 2 * tig);
            float e0 = fmaf((acc[nt][0] - mu0) * rs0, gv.x, bv.x);
            float e1 = fmaf((acc[nt][1] - mu0) * rs0, gv.y, bv.y);
            float e2 = fmaf((acc[nt][2] - mu1) * rs1, gv.x, bv.x);
            float e3 = fmaf((acc[nt][3] - mu1) * rs1, gv.y, bv.y);
            int kk = nt >> 1, of = (nt & 1) * 2;
            sp2(e0, e1, a2h[kk][of],     a2l[kk][of]);
            sp2(e2, e3, a2h[kk][of + 1], a2l[kk][of + 1]);
        }

        // ================= GEMM2: H = relu(LR @ W1^T)  (24 n-tiles, 6 k-tiles) =================
        uint32_t hh[12][4], hl[12][4];
#pragma unroll
        for (int g = 0; g < 6; g++) {
            float ac[4][4];
#pragma unroll
            for (int j = 0; j < 4; j++) { ac[j][0] = ac[j][1] = ac[j][2] = ac[j][3] = 0.f; }
#pragma unroll
            for (int ktp = 0; ktp < 3; ktp++) {
                uint32_t bh[4][4], bl[4][4];
#pragma unroll
                for (int j = 0; j < 4; j++) {
                    int nt = 4 * g + j;
                    LDSM4(bh[j][0], bh[j][1], bh[j][2], bh[j][3], bW1h + nt * (8 * STR_W1) + ktp * 64);
                    LDSM4(bl[j][0], bl[j][1], bl[j][2], bl[j][3], bW1l + nt * (8 * STR_W1) + ktp * 64);
                }
#pragma unroll
                for (int j = 0; j < 4; j++) MMA6(ac[j], a2h[2 * ktp], a2l[2 * ktp], a2h[2 * ktp + 1], a2l[2 * ktp + 1], bh[j], bl[j]);
            }
#pragma unroll
            for (int j = 0; j < 4; j++) {
                int nt = 4 * g + j;
                int kk = nt >> 1, of = (nt & 1) * 2;
                float e0 = fmaxf(ac[j][0], 0.f), e1 = fmaxf(ac[j][1], 0.f);
                float e2 = fmaxf(ac[j][2], 0.f), e3 = fmaxf(ac[j][3], 0.f);
                sp2(e0, e1, hh[kk][of],     hl[kk][of]);
                sp2(e2, e3, hh[kk][of + 1], hl[kk][of + 1]);
            }
        }

        // ================= GEMM3: S = sigmoid(H @ W2^T)  (12 n-tiles, 12 k-tiles) =================
        float sfr[12][4];
#pragma unroll
        for (int g = 0; g < 3; g++) {
            float ac[4][4];
#pragma unroll
            for (int j = 0; j < 4; j++) { ac[j][0] = ac[j][1] = ac[j][2] = ac[j][3] = 0.f; }
#pragma unroll
            for (int ktp = 0; ktp < 6; ktp++) {
                uint32_t bh[4][4], bl[4][4];
#pragma unroll
                for (int j = 0; j < 4; j++) {
                    int nt = 4 * g + j;
                    LDSM4(bh[j][0], bh[j][1], bh[j][2], bh[j][3], bW2h + nt * (8 * STR_W2) + ktp * 64);
                    LDSM4(bl[j][0], bl[j][1], bl[j][2], bl[j][3], bW2l + nt * (8 * STR_W2) + ktp * 64);
                }
#pragma unroll
                for (int j = 0; j < 4; j++) MMA6(ac[j], hh[2 * ktp], hl[2 * ktp], hh[2 * ktp + 1], hl[2 * ktp + 1], bh[j], bl[j]);
            }
#pragma unroll
            for (int j = 0; j < 4; j++) {
#pragma unroll
                for (int i = 0; i < 4; i++)
                    sfr[4 * g + j][i] = 1.0f / (1.0f + __expf(-ac[j][i]));
            }
        }

        // ================= LayerNorm 2 + output =================
        float t0 = 0.f, t1 = 0.f;
#pragma unroll
        for (int nt = 0; nt < 12; nt++) { t0 += sfr[nt][0] + sfr[nt][1]; t1 += sfr[nt][2] + sfr[nt][3]; }
        t0 += __shfl_xor_sync(0xffffffffu, t0, 1); t0 += __shfl_xor_sync(0xffffffffu, t0, 2);
        t1 += __shfl_xor_sync(0xffffffffu, t1, 1); t1 += __shfl_xor_sync(0xffffffffu, t1, 2);
        float m20 = t0 * (1.0f / 96.0f), m21 = t1 * (1.0f / 96.0f);
        float p0 = 0.f, p1 = 0.f;
#pragma unroll
        for (int nt = 0; nt < 12; nt++) {
            float d;
            d = sfr[nt][0] - m20; p0 = fmaf(d, d, p0);
            d = sfr[nt][1] - m20; p0 = fmaf(d, d, p0);
            d = sfr[nt][2] - m21; p1 = fmaf(d, d, p1);
            d = sfr[nt][3] - m21; p1 = fmaf(d, d, p1);
        }
        p0 += __shfl_xor_sync(0xffffffffu, p0, 1); p0 += __shfl_xor_sync(0xffffffffu, p0, 2);
        p1 += __shfl_xor_sync(0xffffffffu, p1, 1); p1 += __shfl_xor_sync(0xffffffffu, p1, 2);
        float rz0 = rsqrtf(p0 * (1.0f / 96.0f) + EPSV);
        float rz1 = rsqrtf(p1 * (1.0f / 96.0f) + EPSV);

#pragma unroll
        for (int nt = 0; nt < 12; nt++) {
            int col = 8 * nt + 2 * tig;
            float2 gv = *(const float2*)(sg  + col);
            float2 bv = *(const float2*)(sbt + col);
            float w00 = fmaf((sfr[nt][0] - m20) * rz0, gv.x, bv.x);
            float w01 = fmaf((sfr[nt][1] - m20) * rz0, gv.y, bv.y);
            float w10 = fmaf((sfr[nt][2] - m21) * rz1, gv.x, bv.x);
            float w11 = fmaf((sfr[nt][3] - m21) * rz1, gv.y, bv.y);
            if (r0 < rows) {
                float2 xv = *(const float2*)(x + (size_t)r0 * NN + col);
                float2 o; o.x = xv.x * w00; o.y = xv.y * w01;
                *(float2*)(out + (size_t)r0 * NN + col) = o;
            }
            if (r1 < rows) {
                float2 xv = *(const float2*)(x + (size_t)r1 * NN + col);
                float2 o; o.x = xv.x * w10; o.y = xv.y * w11;
                *(float2*)(out + (size_t)r1 * NN + col) = o;
            }
        }
    }
}

extern "C" void kernel_launch(void* const* d_in, const int* in_sizes, int n_in,
                              void* d_out, int out_size) {
    const float* x     = (const float*)d_in[0];
    const float* W1    = (const float*)d_in[1];
    const float* W2    = (const float*)d_in[2];
    const float* gamma = (const float*)d_in[3];
    const float* beta  = (const float*)d_in[4];
    float* out = (float*)d_out;

    int rows = in_sizes[0] / NN;

    cudaFuncSetAttribute(fused_mma_kernel, cudaFuncAttributeMaxDynamicSharedMemorySize, SMEM_TOTAL);
    fused_mma_kernel<<<152, TPB, SMEM_TOTAL>>>(x, W1, W2, gamma, beta, out, rows);
}

// round 4
// speedup vs baseline: 18.6126x; 1.1767x over previous
#include <cuda_runtime.h>
#include <cuda_fp16.h>
#include <math.h>
#include <stdint.h>

#define NN   96
#define HH   192
#define TPB  384
#define RPT  (12 * 16)   // rows per CTA tile (12 warps x m16)
#define EPSV 1e-6f

// ---------------- smem layout (bytes) ----------------
#define OFF_G     0                      // float gamma[96]
#define OFF_B     384                    // float beta[96]
#define OFF_DHI   1024
#define STR_D     208                    // 104 f16 per row (conflict-free ldmatrix)
#define SZ_D      (96 * 208)
#define OFF_DLO   (OFF_DHI + SZ_D)
#define OFF_W1HI  (OFF_DLO + SZ_D)
#define STR_W1    208
#define SZ_W1     (192 * 208)
#define OFF_W1LO  (OFF_W1HI + SZ_W1)
#define OFF_W2HI  (OFF_W1LO + SZ_W1)
#define STR_W2    400                    // 200 f16 per row
#define SZ_W2     (96 * 400)
#define OFF_W2LO  (OFF_W2HI + SZ_W2)
#define SMEM_TOTAL (OFF_W2LO + SZ_W2)    // 197632 bytes

__device__ __forceinline__ uint32_t smem_u32(const void* p) {
    uint32_t a;
    asm("{ .reg .u64 t; cvta.to.shared.u64 t, %1; cvt.u32.u64 %0, t; }" : "=r"(a) : "l"(p));
    return a;
}

#define LDSM4(d0, d1, d2, d3, a) \
    asm volatile("ldmatrix.sync.aligned.m8n8.x4.shared.b16 {%0,%1,%2,%3}, [%4];" \
        : "=r"(d0), "=r"(d1), "=r"(d2), "=r"(d3) : "r"(a))

#define MMA(ac, A, b0, b1) \
    asm volatile("mma.sync.aligned.m16n8k16.row.col.f32.f16.f16.f32 " \
        "{%0,%1,%2,%3}, {%4,%5,%6,%7}, {%8,%9}, {%0,%1,%2,%3};" \
        : "+f"((ac)[0]), "+f"((ac)[1]), "+f"((ac)[2]), "+f"((ac)[3]) \
        : "r"((A)[0]), "r"((A)[1]), "r"((A)[2]), "r"((A)[3]), "r"(b0), "r"(b1))

// split (a,b) into packed f16x2 hi and lo (residual) words
__device__ __forceinline__ void sp2(float a, float b, uint32_t& hi, uint32_t& lo) {
    __half2 h = __floats2half2_rn(a, b);
    float ra = a - __low2float(h);
    float rb = b - __high2float(h);
    __half2 l = __floats2half2_rn(ra, rb);
    hi = *(uint32_t*)&h;
    lo = *(uint32_t*)&l;
}

// 6-mma split group over k32: (Ahi*Bhi + Ahi*Blo + Alo*Bhi) x 2 k16-halves
#define MMA6(ac, A0h, A0l, A1h, A1l, B_h, B_l)       \
    do {                                             \
        MMA(ac, A0h, (B_h)[0], (B_h)[1]);            \
        MMA(ac, A0h, (B_l)[0], (B_l)[1]);            \
        MMA(ac, A0l, (B_h)[0], (B_h)[1]);            \
        MMA(ac, A1h, (B_h)[2], (B_h)[3]);            \
        MMA(ac, A1h, (B_l)[2], (B_l)[3]);            \
        MMA(ac, A1l, (B_h)[2], (B_h)[3]);            \
    } while (0)

extern __shared__ char sm[];

__global__ void __launch_bounds__(TPB, 1)
fused_mma_kernel(const float* __restrict__ x,
                 const float* __restrict__ W1,
                 const float* __restrict__ W2,
                 const float* __restrict__ gamma,
                 const float* __restrict__ beta,
                 float* __restrict__ out,
                 int rows) {
    const int tid  = threadIdx.x;
    const int lane = tid & 31;
    const int warp = tid >> 5;
    const int gid  = lane >> 2;
    const int tig  = lane & 3;
    const uint32_t sb = smem_u32(sm);

    float* sg  = (float*)(sm + OFF_G);
    float* sbt = (float*)(sm + OFF_B);

    // ---------------- one-time weight staging ----------------
    if (tid < 96) { sg[tid] = gamma[tid]; sbt[tid] = beta[tid]; }
    const float PI192 = 0.016362461737446838f;
    for (int t = tid; t < 96 * 96; t += TPB) {
        int n = t / 96, i = t % 96;
        int m = ((2 * i + 1) * n) % 384;
        float v = 2.0f * cosf(PI192 * (float)m);
        __half h = __float2half_rn(v);
        __half l = __float2half_rn(v - __half2float(h));
        *(__half*)(sm + OFF_DHI + n * STR_D + i * 2) = h;
        *(__half*)(sm + OFF_DLO + n * STR_D + i * 2) = l;
    }
    for (int t = tid; t < 192 * 96; t += TPB) {
        int n = t / 96, i = t % 96;
        float v = W1[t];
        __half h = __float2half_rn(v);
        __half l = __float2half_rn(v - __half2float(h));
        *(__half*)(sm + OFF_W1HI + n * STR_W1 + i * 2) = h;
        *(__half*)(sm + OFF_W1LO + n * STR_W1 + i * 2) = l;
    }
    for (int t = tid; t < 96 * 192; t += TPB) {
        int n = t / 192, i = t % 192;
        float v = W2[t];
        __half h = __float2half_rn(v);
        __half l = __float2half_rn(v - __half2float(h));
        *(__half*)(sm + OFF_W2HI + n * STR_W2 + i * 2) = h;
        *(__half*)(sm + OFF_W2LO + n * STR_W2 + i * 2) = l;
    }
    __syncthreads();

    const uint32_t lrow = lane & 7;
    const uint32_t lkb  = (uint32_t)(lane >> 3) * 16;
    const uint32_t bDh  = sb + OFF_DHI  + lrow * STR_D  + lkb;
    const uint32_t bDl  = sb + OFF_DLO  + lrow * STR_D  + lkb;
    const uint32_t bW1h = sb + OFF_W1HI + lrow * STR_W1 + lkb;
    const uint32_t bW1l = sb + OFF_W1LO + lrow * STR_W1 + lkb;
    const uint32_t bW2h = sb + OFF_W2HI + lrow * STR_W2 + lkb;
    const uint32_t bW2l = sb + OFF_W2LO + lrow * STR_W2 + lkb;

    const int ntiles = (rows + RPT - 1) / RPT;

    for (int tile = blockIdx.x; tile < ntiles; tile += gridDim.x) {
        const int r0 = tile * RPT + warp * 16 + gid;
        const int r1 = r0 + 8;
        const int r0c = min(r0, rows - 1);
        const int r1c = min(r1, rows - 1);
        const float* xr0 = x + (size_t)r0c * NN;
        const float* xr1 = x + (size_t)r1c * NN;

        // ================= GEMM1: Y = X @ D^T =================
        float acc[12][4];
#pragma unroll
        for (int i = 0; i < 12; i++) { acc[i][0] = acc[i][1] = acc[i][2] = acc[i][3] = 0.f; }

#pragma unroll
        for (int ktp = 0; ktp < 3; ktp++) {
            uint32_t ah0[4], al0[4], ah1[4], al1[4];
            {
                int kb = 32 * ktp + 2 * tig;
                float2 v0 = *(const float2*)(xr0 + kb);
                float2 v1 = *(const float2*)(xr1 + kb);
                float2 v2 = *(const float2*)(xr0 + kb + 8);
                float2 v3 = *(const float2*)(xr1 + kb + 8);
                sp2(v0.x, v0.y, ah0[0], al0[0]);
                sp2(v1.x, v1.y, ah0[1], al0[1]);
                sp2(v2.x, v2.y, ah0[2], al0[2]);
                sp2(v3.x, v3.y, ah0[3], al0[3]);
                float2 u0 = *(const float2*)(xr0 + kb + 16);
                float2 u1 = *(const float2*)(xr1 + kb + 16);
                float2 u2 = *(const float2*)(xr0 + kb + 24);
                float2 u3 = *(const float2*)(xr1 + kb + 24);
                sp2(u0.x, u0.y, ah1[0], al1[0]);
                sp2(u1.x, u1.y, ah1[1], al1[1]);
                sp2(u2.x, u2.y, ah1[2], al1[2]);
                sp2(u3.x, u3.y, ah1[3], al1[3]);
            }
#pragma unroll
            for (int g = 0; g < 3; g++) {
                uint32_t bh[4][4], bl[4][4];
#pragma unroll
                for (int j = 0; j < 4; j++) {
                    int nt = 4 * g + j;
                    LDSM4(bh[j][0], bh[j][1], bh[j][2], bh[j][3], bDh + nt * (8 * STR_D) + ktp * 64);
                    LDSM4(bl[j][0], bl[j][1], bl[j][2], bl[j][3], bDl + nt * (8 * STR_D) + ktp * 64);
                }
#pragma unroll
                for (int j = 0; j < 4; j++) MMA(acc[4 * g + j], ah0, bh[j][0], bh[j][1]);
#pragma unroll
                for (int j = 0; j < 4; j++) MMA(acc[4 * g + j], ah0, bl[j][0], bl[j][1]);
#pragma unroll
                for (int j = 0; j < 4; j++) MMA(acc[4 * g + j], al0, bh[j][0], bh[j][1]);
#pragma unroll
                for (int j = 0; j < 4; j++) MMA(acc[4 * g + j], ah1, bh[j][2], bh[j][3]);
#pragma unroll
                for (int j = 0; j < 4; j++) MMA(acc[4 * g + j], ah1, bl[j][2], bl[j][3]);
#pragma unroll
                for (int j = 0; j < 4; j++) MMA(acc[4 * g + j], al1, bh[j][2], bh[j][3]);
            }
        }

        // ================= LayerNorm 1 =================
        float s0 = 0.f, s1 = 0.f;
#pragma unroll
        for (int nt = 0; nt < 12; nt++) { s0 += acc[nt][0] + acc[nt][1]; s1 += acc[nt][2] + acc[nt][3]; }
        s0 += __shfl_xor_sync(0xffffffffu, s0, 1); s0 += __shfl_xor_sync(0xffffffffu, s0, 2);
        s1 += __shfl_xor_sync(0xffffffffu, s1, 1); s1 += __shfl_xor_sync(0xffffffffu, s1, 2);
        float mu0 = s0 * (1.0f / 96.0f), mu1 = s1 * (1.0f / 96.0f);
        float q0 = 0.f, q1 = 0.f;
#pragma unroll
        for (int nt = 0; nt < 12; nt++) {
            float d;
            d = acc[nt][0] - mu0; q0 = fmaf(d, d, q0);
            d = acc[nt][1] - mu0; q0 = fmaf(d, d, q0);
            d = acc[nt][2] - mu1; q1 = fmaf(d, d, q1);
            d = acc[nt][3] - mu1; q1 = fmaf(d, d, q1);
        }
        q0 += __shfl_xor_sync(0xffffffffu, q0, 1); q0 += __shfl_xor_sync(0xffffffffu, q0, 2);
        q1 += __shfl_xor_sync(0xffffffffu, q1, 1); q1 += __shfl_xor_sync(0xffffffffu, q1, 2);
        float rs0 = rsqrtf(q0 * (1.0f / 96.0f) + EPSV);
        float rs1 = rsqrtf(q1 * (1.0f / 96.0f) + EPSV);

        // LN -> GEMM2 A-fragments (D-frag == A-frag alignment)
        uint32_t a2h[6][4], a2l[6][4];
#pragma unroll
        for (int nt = 0; nt < 12; nt++) {
            float2 gv = *(const float2*)(sg  + 8 * nt + 2 * tig);
            float2 bv = *(const float2*)(sbt + 8 * nt + 2 * tig);
            float e0 = fmaf((acc[nt][0] - mu0) * rs0, gv.x, bv.x);
            float e1 = fmaf((acc[nt][1] - mu0) * rs0, gv.y, bv.y);
            float e2 = fmaf((acc[nt][2] - mu1) * rs1, gv.x, bv.x);
            float e3 = fmaf((acc[nt][3] - mu1) * rs1, gv.y, bv.y);
            int kk = nt >> 1, of = (nt & 1) * 2;
            sp2(e0, e1, a2h[kk][of],     a2l[kk][of]);
            sp2(e2, e3, a2h[kk][of + 1], a2l[kk][of + 1]);
        }

        // ========== Fused GEMM2 (relu) -> GEMM3 streaming over h-chunks ==========
        float sfr[12][4];
#pragma unroll
        for (int i = 0; i < 12; i++) { sfr[i][0] = sfr[i][1] = sfr[i][2] = sfr[i][3] = 0.f; }

#pragma unroll
        for (int g = 0; g < 6; g++) {
            // GEMM2 for n-tiles 4g..4g+3 (K=96)
            float ac2[4][4];
#pragma unroll
            for (int j = 0; j < 4; j++) { ac2[j][0] = ac2[j][1] = ac2[j][2] = ac2[j][3] = 0.f; }
#pragma unroll
            for (int ktp = 0; ktp < 3; ktp++) {
#pragma unroll
                for (int j = 0; j < 4; j++) {
                    uint32_t bh[4], bl[4];
                    int nt = 4 * g + j;
                    LDSM4(bh[0], bh[1], bh[2], bh[3], bW1h + nt * (8 * STR_W1) + ktp * 64);
                    LDSM4(bl[0], bl[1], bl[2], bl[3], bW1l + nt * (8 * STR_W1) + ktp * 64);
                    MMA6(ac2[j], a2h[2 * ktp], a2l[2 * ktp], a2h[2 * ktp + 1], a2l[2 * ktp + 1], bh, bl);
                }
            }
            // relu + pack: n-tiles 4g,4g+1 -> GEMM3 k-tile 2g (h0), 4g+2,4g+3 -> k-tile 2g+1 (h1)
            uint32_t h0h[4], h0l[4], h1h[4], h1l[4];
            {
                float e0, e1, e2, e3;
                e0 = fmaxf(ac2[0][0], 0.f); e1 = fmaxf(ac2[0][1], 0.f);
                e2 = fmaxf(ac2[0][2], 0.f); e3 = fmaxf(ac2[0][3], 0.f);
                sp2(e0, e1, h0h[0], h0l[0]); sp2(e2, e3, h0h[1], h0l[1]);
                e0 = fmaxf(ac2[1][0], 0.f); e1 = fmaxf(ac2[1][1], 0.f);
                e2 = fmaxf(ac2[1][2], 0.f); e3 = fmaxf(ac2[1][3], 0.f);
                sp2(e0, e1, h0h[2], h0l[2]); sp2(e2, e3, h0h[3], h0l[3]);
                e0 = fmaxf(ac2[2][0], 0.f); e1 = fmaxf(ac2[2][1], 0.f);
                e2 = fmaxf(ac2[2][2], 0.f); e3 = fmaxf(ac2[2][3], 0.f);
                sp2(e0, e1, h1h[0], h1l[0]); sp2(e2, e3, h1h[1], h1l[1]);
                e0 = fmaxf(ac2[3][0], 0.f); e1 = fmaxf(ac2[3][1], 0.f);
                e2 = fmaxf(ac2[3][2], 0.f); e3 = fmaxf(ac2[3][3], 0.f);
                sp2(e0, e1, h1h[2], h1l[2]); sp2(e2, e3, h1h[3], h1l[3]);
            }
            // GEMM3 partial update over this k32 chunk (12 n-tiles)
#pragma unroll
            for (int j = 0; j < 12; j++) {
                uint32_t bh[4], bl[4];
                LDSM4(bh[0], bh[1], bh[2], bh[3], bW2h + j * (8 * STR_W2) + g * 64);
                LDSM4(bl[0], bl[1], bl[2], bl[3], bW2l + j * (8 * STR_W2) + g * 64);
                MMA6(sfr[j], h0h, h0l, h1h, h1l, bh, bl);
            }
        }

        // ================= sigmoid + LayerNorm 2 + output =================
#pragma unroll
        for (int nt = 0; nt < 12; nt++) {
#pragma unroll
            for (int i = 0; i < 4; i++)
                sfr[nt][i] = 1.0f / (1.0f + __expf(-sfr[nt][i]));
        }

        float t0 = 0.f, t1 = 0.f;
#pragma unroll
        for (int nt = 0; nt < 12; nt++) { t0 += sfr[nt][0] + sfr[nt][1]; t1 += sfr[nt][2] + sfr[nt][3]; }
        t0 += __shfl_xor_sync(0xffffffffu, t0, 1); t0 += __shfl_xor_sync(0xffffffffu, t0, 2);
        t1 += __shfl_xor_sync(0xffffffffu, t1, 1); t1 += __shfl_xor_sync(0xffffffffu, t1, 2);
        float m20 = t0 * (1.0f / 96.0f), m21 = t1 * (1.0f / 96.0f);
        float p0 = 0.f, p1 = 0.f;
#pragma unroll
        for (int nt = 0; nt < 12; nt++) {
            float d;
            d = sfr[nt][0] - m20; p0 = fmaf(d, d, p0);
            d = sfr[nt][1] - m20; p0 = fmaf(d, d, p0);
            d = sfr[nt][2] - m21; p1 = fmaf(d, d, p1);
            d = sfr[nt][3] - m21; p1 = fmaf(d, d, p1);
        }
        p0 += __shfl_xor_sync(0xffffffffu, p0, 1); p0 += __shfl_xor_sync(0xffffffffu, p0, 2);
        p1 += __shfl_xor_sync(0xffffffffu, p1, 1); p1 += __shfl_xor_sync(0xffffffffu, p1, 2);
        float rz0 = rsqrtf(p0 * (1.0f / 96.0f) + EPSV);
        float rz1 = rsqrtf(p1 * (1.0f / 96.0f) + EPSV);

#pragma unroll
        for (int nt = 0; nt < 12; nt++) {
            int col = 8 * nt + 2 * tig;
            float2 gv = *(const float2*)(sg  + col);
            float2 bv = *(const float2*)(sbt + col);
            float w00 = fmaf((sfr[nt][0] - m20) * rz0, gv.x, bv.x);
            float w01 = fmaf((sfr[nt][1] - m20) * rz0, gv.y, bv.y);
            float w10 = fmaf((sfr[nt][2] - m21) * rz1, gv.x, bv.x);
            float w11 = fmaf((sfr[nt][3] - m21) * rz1, gv.y, bv.y);
            if (r0 < rows) {
                float2 xv = *(const float2*)(x + (size_t)r0 * NN + col);
                float2 o; o.x = xv.x * w00; o.y = xv.y * w01;
                *(float2*)(out + (size_t)r0 * NN + col) = o;
            }
            if (r1 < rows) {
                float2 xv = *(const float2*)(x + (size_t)r1 * NN + col);
                float2 o; o.x = xv.x * w10; o.y = xv.y * w11;
                *(float2*)(out + (size_t)r1 * NN + col) = o;
            }
        }
    }
}

extern "C" void kernel_launch(void* const* d_in, const int* in_sizes, int n_in,
                              void* d_out, int out_size) {
    const float* x     = (const float*)d_in[0];
    const float* W1    = (const float*)d_in[1];
    const float* W2    = (const float*)d_in[2];
    const float* gamma = (const float*)d_in[3];
    const float* beta  = (const float*)d_in[4];
    float* out = (float*)d_out;

    int rows = in_sizes[0] / NN;

    cudaFuncSetAttribute(fused_mma_kernel, cudaFuncAttributeMaxDynamicSharedMemorySize, SMEM_TOTAL);
    fused_mma_kernel<<<152, TPB, SMEM_TOTAL>>>(x, W1, W2, gamma, beta, out, rows);
}